// round 16
// baseline (speedup 1.0000x reference)
#include <cuda_runtime.h>
#include <cuda_bf16.h>
#include <cstdint>

// AddingGaussianBlur: x (64,512,512,3) f32, stds (64,) f32 -> out f32.
//
// Separable (reference's 3x3 kernel depends only on column index):
//   out = inv * sum_{3 rows} h(row),  h[e] = a*(x[e-3]+x[e+3]) + x[e]
//   a = exp(-1/s^2), s = 3*std[b], inv = 1/(3*(1+2a))
//
// R16 = R14 machinery (horizontal-first cp.async.cg 7-slot ring, depth-5,
// 3 LDS.128/row, hm/hc/hp rolling in registers, issue-before-wait, 1
// barrier/row) scheduled as PERSISTENT ROW-STRIPS:
//   - grid = blocksPerSM(occupancy query) x #SMs -> exactly one wave, no tail
//   - each block streams one contiguous strip of global rows (batch-crossing)
//   - batch boundaries handled in registers: hp=Z at li==511, hm=Z at li==0,
//     next batch's coeffs + first h precomputed at the 511-iteration from the
//     already-resident ring slot (no new WAR hazards)

#define H       512
#define NBATCH  64
#define NROWS   (NBATCH * H)    // 32768 global rows
#define ROWW    1536            // floats per image row
#define NT      384             // one thread per float4 chunk
#define NSLOT   7               // ring slots -> 42KB ring

__global__ __launch_bounds__(NT)
void gauss_blur_kernel(const float* __restrict__ x,
                       const float* __restrict__ stds,
                       float* __restrict__ out)
{
    __shared__ __align__(16) float ring[NSLOT][ROWW];

    const int t   = threadIdx.x;
    const int nb  = gridDim.x;
    const int bid = blockIdx.x;

    // contiguous strip [g0, g1) of global rows; first `rem` blocks get +1
    const int base = NROWS / nb;
    const int rem  = NROWS % nb;
    const int g0   = bid * base + (bid < rem ? bid : rem);
    const int len  = base + (bid < rem ? 1 : 0);
    const int g1   = g0 + len;              // exclusive; loads go up to g1

    const uint32_t ring_smem = (uint32_t)__cvta_generic_to_shared(&ring[0][0]) + t * 16u;
    const float4 Z = make_float4(0.0f, 0.0f, 0.0f, 0.0f);
    const bool hasL = (t > 0);
    const bool hasR = (t < NT - 1);

    // Issue global row gr into slot: cp.async.cg when the strip consumes it,
    // empty commit_group otherwise (keeps wait counts static; unread slots).
    auto issue = [&](int gr, int slot) {
        if (gr >= 0 && gr <= g1 && gr < NROWS) {
            const float* src = x + (size_t)gr * ROWW + t * 4;
            const uint32_t dst = ring_smem + slot * (ROWW * 4);
            asm volatile("cp.async.cg.shared.global [%0], [%1], 16;\n"
                         :: "r"(dst), "l"(src));
        }
        asm volatile("cp.async.commit_group;\n");
    };

    // Horizontal pass on the row in `slot`: h[e] = a*(x[e-3]+x[e+3]) + x[e].
    auto hrow = [&](int slot, float aa) -> float4 {
        const float4* rp4 = reinterpret_cast<const float4*>(ring[slot]);
        const float4 C = rp4[t];
        const float4 L = hasL ? rp4[t - 1] : Z;
        const float4 R = hasR ? rp4[t + 1] : Z;
        float4 h;
        h.x = fmaf(aa, L.y + C.w, C.x);
        h.y = fmaf(aa, L.z + R.x, C.y);
        h.z = fmaf(aa, L.w + R.y, C.z);
        h.w = fmaf(aa, C.x + R.z, C.w);
        return h;
    };

    // Prologue: rows g0-1 .. g0+5 into slots 0..6 (7 groups)
    issue(g0 - 1, 0); issue(g0,     1); issue(g0 + 1, 2); issue(g0 + 2, 3);
    issue(g0 + 3, 4); issue(g0 + 4, 5); issue(g0 + 5, 6);

    // coefficients for the starting batch
    float s   = stds[g0 >> 9] * 3.0f;
    float a   = expf(-1.0f / (s * s));
    float inv = 1.0f / (3.0f * (1.0f + 2.0f * a));

    asm volatile("cp.async.wait_group 5;\n");
    __syncthreads();

    float4 hm = ((g0 & 511) == 0) ? Z : hrow(0, a);   // h(row g0-1)
    float4 hc = hrow(1, a);                           // h(row g0)

    int sl_rd = 2;   // slot of row go+1 at iteration r   ((r+2) mod 7)
    int sl_wr = 0;   // slot for row go+6 at iteration r  (r mod 7)

    #pragma unroll 1
    for (int r = 0; r < len; r++) {
        const int go = g0 + r;

        // Issue row go+6 BEFORE waiting (slot last read at iter r-2; the
        // r-1 barrier separates that read from this rewrite).
        issue(go + 6, sl_wr);

        asm volatile("cp.async.wait_group 5;\n");   // row go+1 resident
        __syncthreads();

        const int li = go & 511;
        float4 hp;
        float4 hcn = Z; float an = a, invn = inv;
        const bool cross = (li == 511);
        if (cross) {
            hp = Z;                                   // next row = new batch
            if (go + 1 < NROWS) {                     // prepare next batch
                const float sn = stds[(go + 1) >> 9] * 3.0f;
                an   = expf(-1.0f / (sn * sn));
                invn = 1.0f / (3.0f * (1.0f + 2.0f * an));
                hcn  = hrow(sl_rd, an);               // h(first row, new a)
            }
        } else {
            hp = hrow(sl_rd, a);                      // h(row go+1)
        }

        float4 o;
        o.x = inv * (hm.x + hc.x + hp.x);
        o.y = inv * (hm.y + hc.y + hp.y);
        o.z = inv * (hm.z + hc.z + hp.z);
        o.w = inv * (hm.w + hc.w + hp.w);

        __stcs(&reinterpret_cast<float4*>(out + (size_t)go * ROWW)[t], o);

        if (cross) { a = an; inv = invn; hm = Z;  hc = hcn; }
        else       {                     hm = hc; hc = hp;  }

        sl_rd = (sl_rd + 1 == NSLOT) ? 0 : sl_rd + 1;
        sl_wr = (sl_wr + 1 == NSLOT) ? 0 : sl_wr + 1;
    }
}

extern "C" void kernel_launch(void* const* d_in, const int* in_sizes, int n_in,
                              void* d_out, int out_size)
{
    const float* x    = (const float*)d_in[0];
    const float* stds = (const float*)d_in[1];
    float* out        = (float*)d_out;

    // Exactly one wave: blocksPerSM x #SMs (queries are capture-legal).
    int nsm = 148, bpm = 4;
    cudaDeviceGetAttribute(&nsm, cudaDevAttrMultiProcessorCount, 0);
    cudaOccupancyMaxActiveBlocksPerMultiprocessor(&bpm, gauss_blur_kernel, NT, 0);
    if (nsm <= 0) nsm = 148;
    if (bpm <= 0) bpm = 4;
    int grid = nsm * bpm;
    if (grid > NROWS) grid = NROWS;

    gauss_blur_kernel<<<grid, NT>>>(x, stds, out);
}

// round 17
// speedup vs baseline: 1.0031x; 1.0031x over previous
#include <cuda_runtime.h>
#include <cuda_bf16.h>
#include <cstdint>

// AddingGaussianBlur: x (64,512,512,3) f32, stds (64,) f32 -> out f32.
//
// Separable (reference's 3x3 kernel depends only on column index):
//   out = inv * sum_{3 rows} h(row),  h[e] = a*(x[e-3]+x[e+3]) + x[e]
//   a = exp(-1/s^2), s = 3*std[b], inv = 1/(3*(1+2a))
//
// R17 = R14 machinery unchanged (horizontal-first cp.async.cg 7-slot ring,
// depth-5 waits, issue-before-wait, 3 LDS.128/row, hm/hc/hp in registers,
// 1 barrier/row, ~31 regs -> 5 blocks/SM) with a one-wave decomposition:
// grid (11, 64) = 704 blocks ~ 740 concurrent slots. Strips stay inside one
// batch (no boundary branch, coeffs constant per block), strip = 46-47 rows,
// halo overhead 4.3% of input (vs 12.5% at RPB=16).

#define H       512
#define SPB     11              // strips per batch  -> grid.x
#define ROWW    1536            // floats per image row
#define NT      384             // one thread per float4 chunk
#define NSLOT   7               // ring slots -> 42KB ring

__global__ __launch_bounds__(NT)
void gauss_blur_kernel(const float* __restrict__ x,
                       const float* __restrict__ stds,
                       float* __restrict__ out)
{
    __shared__ __align__(16) float ring[NSLOT][ROWW];

    const int b  = blockIdx.y;
    const int sx = blockIdx.x;
    const int t  = threadIdx.x;

    // strip [i0, i1) of rows within batch b
    const int i0  = (sx * H) / SPB;
    const int i1  = ((sx + 1) * H) / SPB;
    const int len = i1 - i0;

    const float s   = stds[b] * 3.0f;
    const float a   = expf(-1.0f / (s * s));
    const float inv = 1.0f / (3.0f * (1.0f + 2.0f * a));

    const float* __restrict__ xb = x   + (size_t)b * H * ROWW;
    float*       __restrict__ ob = out + (size_t)b * H * ROWW;

    const uint32_t ring_smem = (uint32_t)__cvta_generic_to_shared(&ring[0][0]) + t * 16u;
    const float4 Z = make_float4(0.0f, 0.0f, 0.0f, 0.0f);
    const bool hasL = (t > 0);
    const bool hasR = (t < NT - 1);
    const int  iend = i1;             // last row this strip ever reads

    // Issue one row into the given ring slot. Real cp.async.cg only for rows
    // this strip consumes (gi <= iend); zeros when outside the image;
    // otherwise just an empty commit_group (keeps wait counts static).
    auto issue = [&](int gi, int slot) {
        if (gi <= iend) {
            if ((unsigned)gi < (unsigned)H) {
                const float* src = xb + (size_t)gi * ROWW + t * 4;
                const uint32_t dst = ring_smem + slot * (ROWW * 4);
                asm volatile("cp.async.cg.shared.global [%0], [%1], 16;\n"
                             :: "r"(dst), "l"(src));
            } else {
                reinterpret_cast<float4*>(ring[slot] + t * 4)[0] = Z;
            }
        }
        asm volatile("cp.async.commit_group;\n");
    };

    // Horizontal pass on the row in `slot`: h[e] = a*(x[e-3]+x[e+3]) + x[e].
    auto hrow = [&](int slot) -> float4 {
        const float4* rp4 = reinterpret_cast<const float4*>(ring[slot]);
        const float4 C = rp4[t];
        const float4 L = hasL ? rp4[t - 1] : Z;
        const float4 R = hasR ? rp4[t + 1] : Z;
        float4 h;
        h.x = fmaf(a, L.y + C.w, C.x);
        h.y = fmaf(a, L.z + R.x, C.y);
        h.z = fmaf(a, L.w + R.y, C.z);
        h.w = fmaf(a, C.x + R.z, C.w);
        return h;
    };

    // Prologue: rows i0-1 .. i0+5 into slots 0..6 (7 groups); wait until
    // rows i0-1, i0 landed (5 pending), fence, build hm/hc.
    issue(i0 - 1, 0); issue(i0,     1); issue(i0 + 1, 2); issue(i0 + 2, 3);
    issue(i0 + 3, 4); issue(i0 + 4, 5); issue(i0 + 5, 6);
    asm volatile("cp.async.wait_group 5;\n");
    __syncthreads();

    float4 hm = hrow(0);   // h(row i0-1)  (zeros row if i0==0)
    float4 hc = hrow(1);   // h(row i0)

    int sl_rd = 2;   // slot of row gi+1 at iteration r   ((r+2) mod 7)
    int sl_wr = 0;   // slot for row gi+6 at iteration r  (r mod 7)

    #pragma unroll 1
    for (int r = 0; r < len; r++) {
        const int gi = i0 + r;

        // Issue row gi+6 BEFORE waiting: slot sl_wr held row gi-1, last read
        // at iteration r-2; barrier r-1 separates that read from this write.
        issue(gi + 6, sl_wr);

        // row gi+1's group complete (<=5 groups pending), then fence
        asm volatile("cp.async.wait_group 5;\n");
        __syncthreads();

        const float4 hp = hrow(sl_rd);   // h(row gi+1)

        float4 o;
        o.x = inv * (hm.x + hc.x + hp.x);
        o.y = inv * (hm.y + hc.y + hp.y);
        o.z = inv * (hm.z + hc.z + hp.z);
        o.w = inv * (hm.w + hc.w + hp.w);

        __stcs(&reinterpret_cast<float4*>(ob + (size_t)gi * ROWW)[t], o);

        hm = hc; hc = hp;
        sl_rd = (sl_rd + 1 == NSLOT) ? 0 : sl_rd + 1;
        sl_wr = (sl_wr + 1 == NSLOT) ? 0 : sl_wr + 1;
    }
}

extern "C" void kernel_launch(void* const* d_in, const int* in_sizes, int n_in,
                              void* d_out, int out_size)
{
    const float* x    = (const float*)d_in[0];
    const float* stds = (const float*)d_in[1];
    float* out        = (float*)d_out;

    dim3 grid(SPB, 64);   // (11, 64) = 704 blocks ~ one wave at 5 blocks/SM
    gauss_blur_kernel<<<grid, NT>>>(x, stds, out);
}